// round 16
// baseline (speedup 1.0000x reference)
#include <cuda_runtime.h>
#include <cuda_fp16.h>
#include <stdint.h>
#include <math.h>

#define NG   8
#define NH   512
#define NI   1028
#define NB   128
#define NT   64
#define N3H  1536
#define NTOT (NG*N3H)    // 12288
#define MTOT (NB*NT)     // 8192
#define GH   (NG*NH)     // 4096
#define KPC  1056        // input K padded to 33*32

// ---- global scratch (__device__: allocation-free rule) ----
__device__ __half g_Xp[(size_t)MTOT * KPC];   // t-major rows: t*NB + b
__device__ __half g_Wp[(size_t)NTOT * KPC];   // W_ih fp16 [n][k]
__device__ float  g_h[2][NB * GH];            // fp32 h ping-pong
__device__ __half g_hh[2][NB * GH];           // fp16 h planes for MMA
__device__ int    g_sync[NG];

// ---- helpers ----
__device__ __forceinline__ void mma_f16(float* c, const uint32_t* a, const uint32_t* b) {
    asm volatile(
        "mma.sync.aligned.m16n8k16.row.col.f32.f16.f16.f32 "
        "{%0,%1,%2,%3}, {%4,%5,%6,%7}, {%8,%9}, {%0,%1,%2,%3};"
        : "+f"(c[0]), "+f"(c[1]), "+f"(c[2]), "+f"(c[3])
        : "r"(a[0]), "r"(a[1]), "r"(a[2]), "r"(a[3]), "r"(b[0]), "r"(b[1]));
}
__device__ __forceinline__ void ldsm4(uint32_t* r, uint32_t addr) {
    asm volatile("ldmatrix.sync.aligned.m8n8.x4.shared.b16 {%0,%1,%2,%3}, [%4];"
                 : "=r"(r[0]), "=r"(r[1]), "=r"(r[2]), "=r"(r[3]) : "r"(addr));
}
__device__ __forceinline__ uint32_t smem_u32(const void* p) {
    uint32_t a;
    asm("{ .reg .u64 t; cvta.to.shared.u64 t, %1; cvt.u32.u64 %0, t; }" : "=r"(a) : "l"(p));
    return a;
}
__device__ __forceinline__ void cp16(uint32_t dst, const void* src) {
    asm volatile("cp.async.cg.shared.global [%0], [%1], 16;" :: "r"(dst), "l"(src));
}
#define CP_COMMIT()  asm volatile("cp.async.commit_group;" ::: "memory")
#define CP_WAIT(n)   asm volatile("cp.async.wait_group %0;" :: "n"(n) : "memory")

// ---------------------------------------------------------------------------
__global__ void init_h(const float* __restrict__ h0) {
    int i = blockIdx.x * blockDim.x + threadIdx.x;
    if (i < NB * GH) {
        float v = h0[i];
        g_h[0][i]  = v;
        g_hh[0][i] = __float2half_rn(v);
    }
    if (i < NG) g_sync[i] = 0;
}

// Pack X = concat(a,z) -> fp16 plane, T-MAJOR rows (t*NB + b)
__global__ void pack_x_f16(const float* __restrict__ z, const float* __restrict__ a) {
    size_t idx = (size_t)blockIdx.x * blockDim.x + threadIdx.x;
    if (idx >= (size_t)MTOT * KPC) return;
    int mrow = (int)(idx / KPC), k = (int)(idx % KPC);
    int t = mrow >> 7, b = mrow & 127;
    int msrc = b * NT + t;
    float v = 0.f;
    if (k < 4)       v = a[msrc * 4 + k];
    else if (k < NI) v = z[(size_t)msrc * 1024 + (k - 4)];
    g_Xp[idx] = __float2half_rn(v);
}

// Pack W_ih -> fp16 plane [NTOT][KPC]
__global__ void pack_w_f16(const float* __restrict__ Wih) {
    size_t idx = (size_t)blockIdx.x * blockDim.x + threadIdx.x;
    if (idx >= (size_t)NTOT * KPC) return;
    int n = (int)(idx / KPC), k = (int)(idx % KPC);
    g_Wp[idx] = __float2half_rn((k < NI) ? Wih[(size_t)n * NI + k] : 0.f);
}

// ---------------------------------------------------------------------------
// Fused persistent GRU: 128 CTAs = (g, 32-col chunk), 256 threads.
// Per step t:
//   phase2: hp = h(t) @ Whh^T  (Whh fp16 smem-resident; h frags __ldcg from L2)
//   epilogue: gates (r/z merged X+H accs; n-gate split), h(t+1) + out stores
//   arrive -> phase1(t+1): x_proj slice X(t+1) @ Wih^T (Wih streamed from L2
//   via 3-buf cp.async ring) -- fills the barrier-wait window -> spin -> next.
// ---------------------------------------------------------------------------
#define W_STRIDE 1040
#define W_PLANE  (96 * W_STRIDE)        // 99840: Whh fp16 plane
#define WX_BASE  W_PLANE
#define WX_TILE  (96 * 80)              // 7680: one Wih k32 stage
#define SMEM_GRU (WX_BASE + 3 * WX_TILE)  // 122880

__global__ __launch_bounds__(256) void gru_fused(
    const float* __restrict__ Whh, const float* __restrict__ bhh,
    const float* __restrict__ bih, float* __restrict__ out)
{
    extern __shared__ char sm[];
    const uint32_t sb = smem_u32(sm);

    const int tid  = threadIdx.x;
    const int g    = blockIdx.x >> 4;
    const int c0   = (blockIdx.x & 15) * 32;
    const int warp = tid >> 5, lane = tid & 31;
    const int grp  = lane >> 2, tg = lane & 3;
    const int wm   = warp * 16;

    // ---- Whh -> smem fp16 (rows n = gate*32 + cl) ----
    for (int idx = tid; idx < 96 * 512; idx += 256) {
        const int n = idx >> 9, k = idx & 511;
        const float v = Whh[(size_t)(g * N3H + (n >> 5) * NH + c0 + (n & 31)) * NH + k];
        *(__half*)(sm + n * W_STRIDE + k * 2) = __float2half_rn(v);
    }

    // ---- biases: r/z merged (bih+bhh); n-gate split ----
    float biasR[4][2], biasZ[4][2], biasXn[4][2], biasHn[4][2];
    #pragma unroll
    for (int j = 0; j < 4; ++j)
        #pragma unroll
        for (int p = 0; p < 2; ++p) {
            const int c = g * N3H + c0 + j * 8 + 2 * tg + p;
            biasR[j][p]  = bih[c] + bhh[c];
            biasZ[j][p]  = bih[c + NH] + bhh[c + NH];
            biasXn[j][p] = bih[c + 2 * NH];
            biasHn[j][p] = bhh[c + 2 * NH];
        }
    __syncthreads();

    const int rB  = (lane & 7) + ((lane & 16) ? 8 : 0);
    const uint32_t bko = (lane & 8) ? 16 : 0;
    const int wrb = g * N3H + c0;

    const size_t xR0 = (size_t)(wm + grp) * KPC + 2 * tg;
    const size_t xR1 = xR0 + (size_t)8 * KPC;
    const size_t aR0 = (size_t)(wm + grp) * GH + g * NH + 2 * tg;
    const size_t aR1 = aR0 + (size_t)8 * GH;

    float accA[12][4];   // r(0-3), z(4-7), Xn(8-11)
    float accB[4][4];    // Hn

    auto stageW = [&](int kt) {
        const uint32_t dst = sb + WX_BASE + (kt % 3) * WX_TILE;
        #pragma unroll
        for (int u = 0; u < 2; ++u) {
            const int i = tid + u * 256;
            if (i < 384) {
                const int n = i >> 2, ch = i & 3;
                const char* src = (const char*)
                    &g_Wp[(size_t)(wrb + (n >> 5) * NH + (n & 31)) * KPC] + kt * 64 + ch * 16;
                cp16(dst + n * 80 + ch * 16, src);
            }
        }
        CP_COMMIT();
    };

    auto phase1 = [&](int t) {   // accA = X(t) @ Wih^T  (zero-init)
        #pragma unroll
        for (int i = 0; i < 12; ++i)
            accA[i][0] = accA[i][1] = accA[i][2] = accA[i][3] = 0.f;
        const __half* xp = g_Xp + (size_t)t * NB * KPC;
        auto ldx = [&](uint32_t* f, int kc) {
            const int ko = kc * 16;
            f[0] = __ldcg((const uint32_t*)(xp + xR0 + ko));
            f[1] = __ldcg((const uint32_t*)(xp + xR1 + ko));
            f[2] = __ldcg((const uint32_t*)(xp + xR0 + ko + 8));
            f[3] = __ldcg((const uint32_t*)(xp + xR1 + ko + 8));
        };
        uint32_t ax[2][4];
        ldx(ax[0], 0);
        ldx(ax[1], 1);
        stageW(0);
        stageW(1);
        for (int kt = 0; kt < 33; ++kt) {
            if (kt + 2 < 33) { CP_WAIT(1); __syncthreads(); stageW(kt + 2); }
            else             { CP_WAIT(0); __syncthreads(); }
            const uint32_t wb = sb + WX_BASE + (kt % 3) * WX_TILE + bko;
            #pragma unroll
            for (int ks = 0; ks < 2; ++ks) {
                const int kc = kt * 2 + ks;
                uint32_t ah[4];
                ah[0] = ax[kc & 1][0]; ah[1] = ax[kc & 1][1];
                ah[2] = ax[kc & 1][2]; ah[3] = ax[kc & 1][3];
                if (kc + 2 < 66) ldx(ax[kc & 1], kc + 2);
                const uint32_t wks = wb + ks * 32;
                #pragma unroll
                for (int jp = 0; jp < 6; ++jp) {
                    uint32_t b4[4];
                    ldsm4(b4, wks + (jp * 16 + rB) * 80);
                    mma_f16(accA[jp * 2],     ah, b4);
                    mma_f16(accA[jp * 2 + 1], ah, b4 + 2);
                }
            }
        }
    };

    auto phase2 = [&](int t) {   // accA(r,z) += h @ Whh^T; accB = Hn part
        #pragma unroll
        for (int i = 0; i < 4; ++i)
            accB[i][0] = accB[i][1] = accB[i][2] = accB[i][3] = 0.f;
        const __half* hhp = g_hh[t & 1];
        auto lda = [&](uint32_t* f, int kc) {
            const int ko = kc * 16;
            f[0] = __ldcg((const uint32_t*)(hhp + aR0 + ko));
            f[1] = __ldcg((const uint32_t*)(hhp + aR1 + ko));
            f[2] = __ldcg((const uint32_t*)(hhp + aR0 + ko + 8));
            f[3] = __ldcg((const uint32_t*)(hhp + aR1 + ko + 8));
        };
        uint32_t af[2][4];
        lda(af[0], 0);
        lda(af[1], 1);
        #pragma unroll 4
        for (int kc = 0; kc < 32; ++kc) {
            uint32_t ah[4];
            ah[0] = af[kc & 1][0]; ah[1] = af[kc & 1][1];
            ah[2] = af[kc & 1][2]; ah[3] = af[kc & 1][3];
            if (kc < 30) lda(af[kc & 1], kc + 2);
            const uint32_t kb = kc * 32 + bko;
            #pragma unroll
            for (int jp = 0; jp < 4; ++jp) {
                uint32_t b4[4];
                ldsm4(b4, sb + (jp * 16 + rB) * W_STRIDE + kb);
                mma_f16(accA[jp * 2],     ah, b4);
                mma_f16(accA[jp * 2 + 1], ah, b4 + 2);
            }
            #pragma unroll
            for (int jp = 4; jp < 6; ++jp) {
                uint32_t b4[4];
                ldsm4(b4, sb + (jp * 16 + rB) * W_STRIDE + kb);
                mma_f16(accB[(jp - 4) * 2],     ah, b4);
                mma_f16(accB[(jp - 4) * 2 + 1], ah, b4 + 2);
            }
        }
    };

    phase1(0);

    for (int t = 0; t < NT; ++t) {
        phase2(t);

        // ---- gate epilogue ----
        float* __restrict__ hout = g_h[(t + 1) & 1];
        const float* __restrict__ hin = g_h[t & 1];
        __half* __restrict__ nhh = g_hh[(t + 1) & 1];

        #pragma unroll
        for (int j = 0; j < 4; ++j)
            #pragma unroll
            for (int r = 0; r < 2; ++r) {
                const int row = wm + grp + r * 8;
                const int col = c0 + j * 8 + 2 * tg;
                const size_t hidx = (size_t)row * GH + g * NH + col;
                const float2 ho2 = __ldcg((const float2*)&hin[hidx]);
                float2 hn2;
                #pragma unroll
                for (int p = 0; p < 2; ++p) {
                    const float rpre = accA[j    ][r * 2 + p] + biasR[j][p];
                    const float zpre = accA[j + 4][r * 2 + p] + biasZ[j][p];
                    const float xn   = accA[j + 8][r * 2 + p] + biasXn[j][p];
                    const float hn   = accB[j    ][r * 2 + p] + biasHn[j][p];
                    const float ho = p ? ho2.y : ho2.x;
                    const float rr = 1.f / (1.f + __expf(-rpre));
                    const float uu = 1.f / (1.f + __expf(-zpre));
                    const float nn = tanhf(xn + rr * hn);
                    const float hw = (1.f - uu) * nn + uu * ho;
                    if (p == 0) hn2.x = hw; else hn2.y = hw;
                }
                *(float2*)&hout[hidx] = hn2;
                __half2 h2;
                h2.x = __float2half_rn(hn2.x);
                h2.y = __float2half_rn(hn2.y);
                *(__half2*)&nhh[hidx] = h2;
                *(float2*)&out[(size_t)(row * NT + t) * GH + g * NH + col] = hn2;
            }

        // ---- arrive, fill wait window with phase1(t+1), then spin ----
        __threadfence();
        __syncthreads();
        if (tid == 0) atomicAdd(&g_sync[g], 1);
        if (t + 1 < NT) phase1(t + 1);
        if (tid == 0) {
            const int target = 16 * (t + 1);
            while (*(volatile int*)&g_sync[g] < target) { __nanosleep(32); }
        }
        __syncthreads();
    }
}

// ---------------------------------------------------------------------------
extern "C" void kernel_launch(void* const* d_in, const int* in_sizes, int n_in,
                              void* d_out, int out_size) {
    const float* z   = (const float*)d_in[0];
    const float* a   = (const float*)d_in[1];
    const float* h   = (const float*)d_in[2];
    const float* Wih = (const float*)d_in[3];
    const float* Whh = (const float*)d_in[4];
    const float* bih = (const float*)d_in[5];
    const float* bhh = (const float*)d_in[6];
    float* out = (float*)d_out;

    init_h<<<(NB * GH + 255) / 256, 256>>>(h);

    {
        size_t nx = (size_t)MTOT * KPC;
        pack_x_f16<<<(int)((nx + 255) / 256), 256>>>(z, a);
        size_t nw = (size_t)NTOT * KPC;
        pack_w_f16<<<(int)((nw + 255) / 256), 256>>>(Wih);
    }

    cudaFuncSetAttribute(gru_fused, cudaFuncAttributeMaxDynamicSharedMemorySize, SMEM_GRU);
    gru_fused<<<128, 256, SMEM_GRU>>>(Whh, bhh, bih, out);
}

// round 17
// speedup vs baseline: 1.5124x; 1.5124x over previous
#include <cuda_runtime.h>
#include <cuda_fp16.h>
#include <stdint.h>
#include <math.h>

#define NG   8
#define NH   512
#define NI   1028
#define NB   128
#define NT   64
#define N3H  1536
#define NTOT (NG*N3H)    // 12288
#define MTOT (NB*NT)     // 8192
#define GH   (NG*NH)     // 4096
#define KPC  1056        // K padded to 33 * 32
#define KT32 33

// ---- global scratch (__device__: allocation-free rule) ----
__device__ __half g_Xp[(size_t)MTOT * KPC];
__device__ __half g_Wp[(size_t)NTOT * KPC];
__device__ float  g_xproj[(size_t)MTOT * NTOT];
__device__ float  g_h[2][NB * GH];          // fp32 h ping-pong
__device__ __half g_hh[2][NB * GH];         // fp16 h planes for MMA
__device__ int    g_sync[NG];

// ---- helpers ----
__device__ __forceinline__ void mma_f16(float* c, const uint32_t* a, const uint32_t* b) {
    asm volatile(
        "mma.sync.aligned.m16n8k16.row.col.f32.f16.f16.f32 "
        "{%0,%1,%2,%3}, {%4,%5,%6,%7}, {%8,%9}, {%0,%1,%2,%3};"
        : "+f"(c[0]), "+f"(c[1]), "+f"(c[2]), "+f"(c[3])
        : "r"(a[0]), "r"(a[1]), "r"(a[2]), "r"(a[3]), "r"(b[0]), "r"(b[1]));
}
__device__ __forceinline__ void ldsm4(uint32_t* r, uint32_t addr) {
    asm volatile("ldmatrix.sync.aligned.m8n8.x4.shared.b16 {%0,%1,%2,%3}, [%4];"
                 : "=r"(r[0]), "=r"(r[1]), "=r"(r[2]), "=r"(r[3]) : "r"(addr));
}
__device__ __forceinline__ uint32_t smem_u32(const void* p) {
    uint32_t a;
    asm("{ .reg .u64 t; cvta.to.shared.u64 t, %1; cvt.u32.u64 %0, t; }" : "=r"(a) : "l"(p));
    return a;
}
__device__ __forceinline__ void cp16(uint32_t dst, const void* src) {
    asm volatile("cp.async.cg.shared.global [%0], [%1], 16;" :: "r"(dst), "l"(src));
}
#define CP_COMMIT()  asm volatile("cp.async.commit_group;" ::: "memory")
#define CP_WAIT(n)   asm volatile("cp.async.wait_group %0;" :: "n"(n) : "memory")

// ---------------------------------------------------------------------------
__global__ void init_h(const float* __restrict__ h0) {
    int i = blockIdx.x * blockDim.x + threadIdx.x;
    if (i < NB * GH) {
        float v = h0[i];
        g_h[0][i]  = v;
        g_hh[0][i] = __float2half_rn(v);
    }
    if (i < NG) g_sync[i] = 0;
}

// Pack X = concat(a,z) -> fp16 plane [MTOT][KPC], rows m = b*NT + t
__global__ void pack_x_f16(const float* __restrict__ z, const float* __restrict__ a) {
    size_t idx = (size_t)blockIdx.x * blockDim.x + threadIdx.x;
    if (idx >= (size_t)MTOT * KPC) return;
    int m = (int)(idx / KPC), k = (int)(idx % KPC);
    float v = 0.f;
    if (k < 4)       v = a[m * 4 + k];
    else if (k < NI) v = z[(size_t)m * 1024 + (k - 4)];
    g_Xp[idx] = __float2half_rn(v);
}

// Pack W_ih -> fp16 plane [NTOT][KPC]
__global__ void pack_w_f16(const float* __restrict__ Wih) {
    size_t idx = (size_t)blockIdx.x * blockDim.x + threadIdx.x;
    if (idx >= (size_t)NTOT * KPC) return;
    int n = (int)(idx / KPC), k = (int)(idx % KPC);
    g_Wp[idx] = __float2half_rn((k < NI) ? Wih[(size_t)n * NI + k] : 0.f);
}

// ---------------------------------------------------------------------------
// xproj = X @ W^T + b, fp16, fp32 accum. (R11 version: 4-stage cp.async,
// prefetch distance 2, one sync per k-tile — measured 735us)
// ---------------------------------------------------------------------------
#define ROWB   80
#define PLANE  (128 * ROWB)      // 10240 B
#define STG    (2 * PLANE)       // 20480 B per stage
#define XS_SMEM (4 * STG)        // 81920 B

__global__ __launch_bounds__(256) void xproj_f16(const float* __restrict__ bih) {
    extern __shared__ char smem[];
    const uint32_t sb = smem_u32(smem);
    const int tid = threadIdx.x, lane = tid & 31, warp = tid >> 5;
    const int m0 = blockIdx.y * 128, n0 = blockIdx.x * 128;
    const int wm = (warp & 1) * 64, wn = (warp >> 1) * 32;
    const int grp = lane >> 2, tg = lane & 3;

    float c[4][4][4] = {};

    auto stage = [&](int kt) {
        const uint32_t dst0 = sb + (kt & 3) * STG;
        #pragma unroll
        for (int u = 0; u < 4; ++u) {
            const int i = tid + u * 256;
            const int s = i >> 9;
            const int r = (i >> 2) & 127;
            const int ch = i & 3;
            const char* src = s
                ? (const char*)&g_Wp[(size_t)(n0 + r) * KPC]
                : (const char*)&g_Xp[(size_t)(m0 + r) * KPC];
            cp16(dst0 + s * PLANE + r * ROWB + ch * 16, src + kt * 64 + ch * 16);
        }
        CP_COMMIT();
    };

    stage(0);
    stage(1);

    const int rowA = wm + (lane & 15);
    const int kAoff = (lane & 16) ? 16 : 0;
    const int rowB = wn + (lane & 7) + ((lane & 16) ? 8 : 0);
    const int kBoff = (lane & 8) ? 16 : 0;

    for (int kt = 0; kt < KT32; ++kt) {
        if (kt + 2 < KT32) { stage(kt + 2); CP_WAIT(2); }
        else if (kt + 1 < KT32) { CP_WAIT(1); }
        else { CP_WAIT(0); }
        __syncthreads();

        const uint32_t base = sb + (kt & 3) * STG;
        #pragma unroll
        for (int ks = 0; ks < 2; ++ks) {
            uint32_t ah[4][4], bh[4][2];
            #pragma unroll
            for (int mi = 0; mi < 4; ++mi)
                ldsm4(ah[mi], base + (rowA + mi * 16) * ROWB + ks * 32 + kAoff);
            #pragma unroll
            for (int np = 0; np < 2; ++np) {
                uint32_t t4[4];
                ldsm4(t4, base + PLANE + (rowB + np * 16) * ROWB + ks * 32 + kBoff);
                bh[np * 2][0] = t4[0]; bh[np * 2][1] = t4[1];
                bh[np * 2 + 1][0] = t4[2]; bh[np * 2 + 1][1] = t4[3];
            }
            #pragma unroll
            for (int mi = 0; mi < 4; ++mi)
                #pragma unroll
                for (int nj = 0; nj < 4; ++nj)
                    mma_f16(c[mi][nj], ah[mi], bh[nj]);
        }
    }

    #pragma unroll
    for (int nj = 0; nj < 4; ++nj) {
        const int col = n0 + wn + nj * 8 + 2 * tg;
        const float b0v = bih[col], b1v = bih[col + 1];
        #pragma unroll
        for (int mi = 0; mi < 4; ++mi) {
            const int r0 = m0 + wm + mi * 16 + grp;
            float2 v0 = make_float2(c[mi][nj][0] + b0v, c[mi][nj][1] + b1v);
            float2 v1 = make_float2(c[mi][nj][2] + b0v, c[mi][nj][3] + b1v);
            *(float2*)&g_xproj[(size_t)r0 * NTOT + col]       = v0;
            *(float2*)&g_xproj[(size_t)(r0 + 8) * NTOT + col] = v1;
        }
    }
}

// ---------------------------------------------------------------------------
// Persistent recurrence, 512 threads / 16 warps.
// warp = (batch-group bg = w>>1 [16 rows], column-half ch = w&1 [16 cols]).
// Per kc each warp: 3 LDSM + 6 MMA (all three gates for its 16 cols) —
// half the per-warp chain of the 8-warp version, 4 warps/SMSP for latency
// hiding. h fragments __ldcg from L2 with prefetch depth 4. Gate-aligned.
// ---------------------------------------------------------------------------
#define W_STRIDE 1040
#define SMEM_GRU (96 * W_STRIDE)        // 99840

__global__ __launch_bounds__(512) void gru_persistent(
    const float* __restrict__ Whh, const float* __restrict__ bhh,
    float* __restrict__ out)
{
    extern __shared__ char sm[];
    const uint32_t sb = smem_u32(sm);

    const int tid  = threadIdx.x;
    const int g    = blockIdx.x >> 4;
    const int c0   = (blockIdx.x & 15) * 32;
    const int warp = tid >> 5, lane = tid & 31;
    const int grp  = lane >> 2, tg = lane & 3;
    const int bg   = warp >> 1;          // batch group 0..7
    const int ch   = warp & 1;           // column half 0..1
    const int wm   = bg * 16;

    // ---- Fill W plane once (rows n = gate*32 + cl, cols k) ----
    for (int idx = tid; idx < 96 * 512; idx += 512) {
        const int n = idx >> 9, k = idx & 511;
        const float v = Whh[(size_t)(g * N3H + (n >> 5) * NH + c0 + (n & 31)) * NH + k];
        *(__half*)(sm + n * W_STRIDE + k * 2) = __float2half_rn(v);
    }

    // ---- Loop-invariant biases: [gate][frag][pair] for this warp's 16 cols
    float bias[3][2][2];
    #pragma unroll
    for (int gate = 0; gate < 3; ++gate)
        #pragma unroll
        for (int jf = 0; jf < 2; ++jf) {
            const int c = g * N3H + gate * NH + c0 + ch * 16 + jf * 8 + 2 * tg;
            bias[gate][jf][0] = bhh[c];
            bias[gate][jf][1] = bhh[c + 1];
        }
    __syncthreads();

    // ldmatrix B row base: this warp's 16-row tile within each gate's 32 rows
    const int rBase = ch * 16 + (lane & 7) + ((lane & 16) ? 8 : 0);
    const uint32_t bko = (lane & 8) ? 16 : 0;

    // A-fragment global offsets (rows wm+grp, wm+grp+8)
    const size_t aR0 = (size_t)(wm + grp) * GH + g * NH + 2 * tg;
    const size_t aR1 = aR0 + (size_t)8 * GH;

    for (int t = 0; t < NT; ++t) {
        const __half* __restrict__ hhp = g_hh[t & 1];
        const float* __restrict__ hin = g_h[t & 1];

        auto lda = [&](uint32_t* f, int kc) {
            const int ko = kc * 16;
            f[0] = __ldcg((const uint32_t*)(hhp + aR0 + ko));
            f[1] = __ldcg((const uint32_t*)(hhp + aR1 + ko));
            f[2] = __ldcg((const uint32_t*)(hhp + aR0 + ko + 8));
            f[3] = __ldcg((const uint32_t*)(hhp + aR1 + ko + 8));
        };

        float acc[3][2][4] = {};   // [gate][n-frag][c-frag]
        uint32_t af[4][4];
        lda(af[0], 0);
        lda(af[1], 1);
        lda(af[2], 2);
        lda(af[3], 3);

        #pragma unroll 4
        for (int kc = 0; kc < 32; ++kc) {
            uint32_t ah[4];
            ah[0] = af[kc & 3][0]; ah[1] = af[kc & 3][1];
            ah[2] = af[kc & 3][2]; ah[3] = af[kc & 3][3];
            if (kc < 28) lda(af[kc & 3], kc + 4);

            const uint32_t kb = kc * 32 + bko;
            #pragma unroll
            for (int gt = 0; gt < 3; ++gt) {
                uint32_t b4[4];
                ldsm4(b4, sb + (gt * 32 + rBase) * W_STRIDE + kb);
                mma_f16(acc[gt][0], ah, b4);
                mma_f16(acc[gt][1], ah, b4 + 2);
            }
        }

        // ---- Gate epilogue ----
        float* __restrict__ hout = g_h[(t + 1) & 1];
        __half* __restrict__ nhh = g_hh[(t + 1) & 1];

        #pragma unroll
        for (int jf = 0; jf < 2; ++jf)
            #pragma unroll
            for (int r = 0; r < 2; ++r) {
                const int row = wm + grp + r * 8;
                const int col = c0 + ch * 16 + jf * 8 + 2 * tg;
                const size_t hidx = (size_t)row * GH + g * NH + col;
                const size_t xb = (size_t)(row * NT + t) * NTOT + g * N3H;
                const float2 xr2 = *(const float2*)&g_xproj[xb + col];
                const float2 xz2 = *(const float2*)&g_xproj[xb + NH + col];
                const float2 xn2 = *(const float2*)&g_xproj[xb + 2 * NH + col];
                const float2 ho2 = __ldcg((const float2*)&hin[hidx]);
                float2 hn2;
                #pragma unroll
                for (int p = 0; p < 2; ++p) {
                    const float hr = acc[0][jf][r * 2 + p] + bias[0][jf][p];
                    const float hz = acc[1][jf][r * 2 + p] + bias[1][jf][p];
                    const float hnv= acc[2][jf][r * 2 + p] + bias[2][jf][p];
                    const float xr = p ? xr2.y : xr2.x;
                    const float xz = p ? xz2.y : xz2.x;
                    const float xn = p ? xn2.y : xn2.x;
                    const float ho = p ? ho2.y : ho2.x;
                    const float rr = 1.f / (1.f + __expf(-(xr + hr)));
                    const float uu = 1.f / (1.f + __expf(-(xz + hz)));
                    const float nn = tanhf(xn + rr * hnv);
                    const float hw = (1.f - uu) * nn + uu * ho;
                    if (p == 0) hn2.x = hw; else hn2.y = hw;
                }
                *(float2*)&hout[hidx] = hn2;
                __half2 h2;
                h2.x = __float2half_rn(hn2.x);
                h2.y = __float2half_rn(hn2.y);
                *(__half2*)&nhh[hidx] = h2;
                *(float2*)&out[(size_t)(row * NT + t) * GH + g * NH + col] = hn2;
            }

        // ---- group barrier: 16 CTAs of block g ----
        __threadfence();
        __syncthreads();
        if (tid == 0) {
            atomicAdd(&g_sync[g], 1);
            const int target = 16 * (t + 1);
            while (*(volatile int*)&g_sync[g] < target) { __nanosleep(32); }
        }
        __syncthreads();
    }
}

// ---------------------------------------------------------------------------
extern "C" void kernel_launch(void* const* d_in, const int* in_sizes, int n_in,
                              void* d_out, int out_size) {
    const float* z   = (const float*)d_in[0];
    const float* a   = (const float*)d_in[1];
    const float* h   = (const float*)d_in[2];
    const float* Wih = (const float*)d_in[3];
    const float* Whh = (const float*)d_in[4];
    const float* bih = (const float*)d_in[5];
    const float* bhh = (const float*)d_in[6];
    float* out = (float*)d_out;

    init_h<<<(NB * GH + 255) / 256, 256>>>(h);

    {
        size_t nx = (size_t)MTOT * KPC;
        pack_x_f16<<<(int)((nx + 255) / 256), 256>>>(z, a);
        size_t nw = (size_t)NTOT * KPC;
        pack_w_f16<<<(int)((nw + 255) / 256), 256>>>(Wih);
    }

    cudaFuncSetAttribute(xproj_f16, cudaFuncAttributeMaxDynamicSharedMemorySize, XS_SMEM);
    dim3 grid(NTOT / 128, MTOT / 128);   // (96, 64)
    xproj_f16<<<grid, 256, XS_SMEM>>>(bih);

    cudaFuncSetAttribute(gru_persistent, cudaFuncAttributeMaxDynamicSharedMemorySize, SMEM_GRU);
    gru_persistent<<<128, 512, SMEM_GRU>>>(Whh, bhh, out);
}